// round 9
// baseline (speedup 1.0000x reference)
#include <cuda_runtime.h>
#include <cuda_fp16.h>
#include <cstdint>

#define S_ 512
#define B_ 64
#define D_ 1024
#define H_ 1024
#define G4_ 4096
#define HB_ (B_ * H_)
#define PRE_T (B_ * G4_)
#define NCTA 128
#define TPB 256

// ---------------- persistent device scratch ----------------
__device__ __half g_Wih0h [G4_ * D_];
__device__ __half g_Wih0l [G4_ * D_];
__device__ __half g_Whh0h [G4_ * H_];
__device__ __half g_Whh0l [G4_ * H_];
__device__ __half g_Wcat1h[G4_ * 2 * H_];
__device__ __half g_Wcat1l[G4_ * 2 * H_];
__device__ float  g_pre0f [(size_t)S_ * PRE_T];   // 512 MB fp32
__device__ float  g_hr0f[2][HB_];
__device__ float  g_hr1f[2][HB_];
__device__ float2 g_p0[2][B_][NCTA];
__device__ float2 g_p1[2][B_][NCTA];
__device__ unsigned g_barcnt;

// ---------------- SMEM layout (bytes) ----------------
#define SW1_OFF   0        // 32*2056 half = 131584
#define SW0_OFF   131584   // 32*1032 half = 66048
#define SAHI_OFF  197632   // 64*66 half = 8448 (zbuf aliases here)
#define SALO_OFF  206080   // 8448
#define SWLO_OFF  214528   // 32*72 half = 4608
#define SG0_OFF   219136   // 1024 f = 4096
#define SBE0_OFF  223232   // 4096
#define ST_OFF    227328   // 6*64 f = 1536
#define BS_OFF    228864   // 64 f = 256
#define SMEM_BYTES 229120

__device__ __forceinline__ void mma16816(float* c,
    uint32_t a0, uint32_t a1, uint32_t a2, uint32_t a3, uint32_t b0, uint32_t b1)
{
    asm volatile(
        "mma.sync.aligned.m16n8k16.row.col.f32.f16.f16.f32 "
        "{%0,%1,%2,%3}, {%4,%5,%6,%7}, {%8,%9}, {%0,%1,%2,%3};\n"
        : "+f"(c[0]), "+f"(c[1]), "+f"(c[2]), "+f"(c[3])
        : "r"(a0), "r"(a1), "r"(a2), "r"(a3), "r"(b0), "r"(b1));
}
__device__ __forceinline__ float sigf_(float x) { return 1.0f / (1.0f + __expf(-x)); }

__device__ __forceinline__ void gbar(unsigned& target) {
    __syncthreads();
    if (threadIdx.x == 0) {
        __threadfence();
        atomicAdd(&g_barcnt, 1u);
        target += NCTA;
        volatile unsigned* p = &g_barcnt;
        unsigned spins = 0;
        while (*p < target) {
            __nanosleep(32);
            if (++spins > 100000000u) break;   // convert pathological hang into visible failure
        }
        __threadfence();
    }
    __syncthreads();
}

// deterministic stats: sum 128 CTA partials in fixed order
__device__ __forceinline__ void finalize_stats(const float2* p, float* m, float* rs, int tid) {
    int b = tid >> 2, q = tid & 3;
    const float2* src = p + b * NCTA + q * 32;
    float s = 0.f, ss = 0.f;
    #pragma unroll
    for (int i = 0; i < 32; i++) { float2 v = __ldcg(src + i); s += v.x; ss += v.y; }
    s += __shfl_xor_sync(~0u, s, 1); ss += __shfl_xor_sync(~0u, ss, 1);
    s += __shfl_xor_sync(~0u, s, 2); ss += __shfl_xor_sync(~0u, ss, 2);
    if (q == 0) {
        float mm = s * (1.0f / H_);
        float var = ss * (1.0f / H_) - mm * mm;
        m[b] = mm; rs[b] = rsqrtf(var + 1e-5f);
    }
}

// split 16 fp32 values into hi/lo fp16 and store in staged A buffers
__device__ __forceinline__ void stage_store(__half* sAhi, __half* sAlo, int sb, int skq,
                                            const float* v)
{
    __half2* dh = (__half2*)(sAhi + sb * 66 + skq);
    __half2* dl = (__half2*)(sAlo + sb * 66 + skq);
    #pragma unroll
    for (int i = 0; i < 8; i++) {
        float x = v[2*i], y = v[2*i+1];
        __half hx = __float2half_rn(x), hy = __float2half_rn(y);
        __half lx = __float2half_rn(x - __half2float(hx));
        __half ly = __float2half_rn(y - __half2float(hy));
        dh[i] = __halves2half2(hx, hy);
        dl[i] = __halves2half2(lx, ly);
    }
}

// ---------------- init ----------------
__global__ __launch_bounds__(1024) void init_all(
    const float* __restrict__ Wih0, const float* __restrict__ Whh0,
    const float* __restrict__ Wih1, const float* __restrict__ Whh1)
{
    int i = blockIdx.x * blockDim.x + threadIdx.x;   // covers 8,388,608
    {
        int n = i >> 11, k = i & 2047;
        float w = (k < 1024) ? Wih1[n * 1024 + k] : Whh1[n * 1024 + (k - 1024)];
        __half hi = __float2half_rn(w);
        g_Wcat1h[i] = hi;
        g_Wcat1l[i] = __float2half_rn(w - __half2float(hi));
    }
    if (i < G4_ * D_) {
        float w = Wih0[i];
        __half hi = __float2half_rn(w);
        g_Wih0h[i] = hi;
        g_Wih0l[i] = __float2half_rn(w - __half2float(hi));
        w = Whh0[i];
        hi = __float2half_rn(w);
        g_Whh0h[i] = hi;
        g_Whh0l[i] = __float2half_rn(w - __half2float(hi));
    }
    if (i == 0) g_barcnt = 0u;
}

// ---------------- pre0f = X @ Wih0^T (fp32 out, hi/lo 3-MMA) ----------------
__global__ __launch_bounds__(256) void pre_gemm(const float* __restrict__ X)
{
    int n0 = blockIdx.x << 6;
    size_t m0 = (size_t)blockIdx.y << 7;
    int w = threadIdx.x >> 5, lane = threadIdx.x & 31;
    int g = lane >> 2, t = lane & 3;
    size_t mr = m0 + (w << 4) + g;

    const float* X0 = X + mr * D_ + (t << 1);
    const float* X1 = X0 + 8 * D_;

    float acc[8][4];
    #pragma unroll
    for (int s = 0; s < 8; s++) { acc[s][0]=acc[s][1]=acc[s][2]=acc[s][3]=0.f; }

    for (int k = 0; k < D_; k += 16) {
        uint32_t ah[4], al[4];
        float2 f;
        #pragma unroll
        for (int q = 0; q < 4; q++) {
            const float* src = (q & 1) ? X1 : X0;
            int ko = k + ((q >> 1) << 3);
            f = *(const float2*)(src + ko);
            __half hx = __float2half_rn(f.x), hy = __float2half_rn(f.y);
            __half lx = __float2half_rn(f.x - __half2float(hx));
            __half ly = __float2half_rn(f.y - __half2float(hy));
            __half2 hh = __halves2half2(hx, hy), ll = __halves2half2(lx, ly);
            ah[q] = *(uint32_t*)&hh; al[q] = *(uint32_t*)&ll;
        }
        #pragma unroll
        for (int s = 0; s < 8; s++) {
            size_t roff = (size_t)(n0 + s * 8 + g) * D_ + (t << 1) + k;
            uint32_t bh0 = *(const uint32_t*)(g_Wih0h + roff);
            uint32_t bh1 = *(const uint32_t*)(g_Wih0h + roff + 8);
            uint32_t bl0 = *(const uint32_t*)(g_Wih0l + roff);
            uint32_t bl1 = *(const uint32_t*)(g_Wih0l + roff + 8);
            mma16816(acc[s], ah[0], ah[1], ah[2], ah[3], bh0, bh1);
            mma16816(acc[s], al[0], al[1], al[2], al[3], bh0, bh1);
            mma16816(acc[s], ah[0], ah[1], ah[2], ah[3], bl0, bl1);
        }
    }
    #pragma unroll
    for (int s = 0; s < 8; s++) {
        int col = n0 + s * 8 + (t << 1);
        *(float2*)&g_pre0f[mr * G4_ + col]       = make_float2(acc[s][0], acc[s][1]);
        *(float2*)&g_pre0f[(mr + 8) * G4_ + col] = make_float2(acc[s][2], acc[s][3]);
    }
}

// ---------------- the persistent recurrence kernel ----------------
__global__ __launch_bounds__(TPB, 1) void lstm_persist(
    const float* __restrict__ bih0, const float* __restrict__ bhh0,
    const float* __restrict__ g0f,  const float* __restrict__ be0f,
    const float* __restrict__ bih1, const float* __restrict__ bhh1,
    const float* __restrict__ g1f,  const float* __restrict__ be1f,
    float* __restrict__ out, int has_tail)
{
    extern __shared__ __align__(16) char smem[];
    __half* sw1  = (__half*)(smem + SW1_OFF);
    __half* sw0  = (__half*)(smem + SW0_OFF);
    __half* sAhi = (__half*)(smem + SAHI_OFF);
    __half* sAlo = (__half*)(smem + SALO_OFF);
    __half* sWlo = (__half*)(smem + SWLO_OFF);
    float*  zbuf = (float*)(smem + SAHI_OFF);   // alias (used post-gemm)
    float*  sg0  = (float*)(smem + SG0_OFF);
    float*  sbe0 = (float*)(smem + SBE0_OFF);
    float*  m0s  = (float*)(smem + ST_OFF);
    float*  rs0s = m0s + 64;
    float*  m1s  = m0s + 128;
    float*  rs1s = m0s + 192;
    float*  b0sum = (float*)(smem + BS_OFF);
    float*  b1sum = b0sum + 32;

    const int tid = threadIdx.x;
    const int cta = blockIdx.x;
    const int j0 = cta << 3;
    const int lane = tid & 31, wid = tid >> 5;
    const int fg = lane >> 2, ft = lane & 3;
    const int wn = wid & 3, wm = wid >> 2;       // 4 n-groups x 2 m-groups
    // gates mapping: thread -> (batch gb, column pair gjj)
    const int gb = tid >> 2;
    const int gjj = (tid & 3) << 1;
    const int gj = j0 + gjj;
    // staging mapping
    const int sb = tid >> 2;                     // batch row
    const int skq = (tid & 3) << 4;              // 16 halves per thread
    // Wlo staging mapping
    const int wr = tid >> 3, wseg = tid & 7;
    const int wRglob = ((wr >> 3) << 10) + j0 + (wr & 7);

    // ---- preload SMEM ----
    for (int idx = tid; idx < 32 * 128; idx += TPB) {
        int n = idx >> 7, kc = (idx & 127) << 3;
        int row = ((n >> 3) << 10) + j0 + (n & 7);
        *(int4*)&sw0[n * 1032 + kc] = *(const int4*)&g_Whh0h[(size_t)row * 1024 + kc];
    }
    for (int idx = tid; idx < 32 * 256; idx += TPB) {
        int n = idx >> 8, kc = (idx & 255) << 3;
        int row = ((n >> 3) << 10) + j0 + (n & 7);
        *(int4*)&sw1[n * 2056 + kc] = *(const int4*)&g_Wcat1h[(size_t)row * 2048 + kc];
    }
    for (int idx = tid; idx < 1024; idx += TPB) {
        sg0[idx] = g0f[idx]; sbe0[idx] = be0f[idx];
    }
    if (tid < 32) {
        int col = ((tid >> 3) << 10) + j0 + (tid & 7);
        b0sum[tid] = bih0[col] + bhh0[col];
        b1sum[tid] = bih1[col] + bhh1[col];
    }
    __syncthreads();

    float c0r[2] = {0.f, 0.f}, c1r[2] = {0.f, 0.f};
    unsigned target = 0;

    for (int t = 0; t < S_; t++) {
        const int par = t & 1, parp = par ^ 1;

        // ================= PHASE A =================
        if (t > 0) {
            finalize_stats(&g_p1[parp][0][0], m1s, rs1s, tid);
            __syncthreads();
            float2 h1v = *(const float2*)&g_hr1f[parp][gb * H_ + gj];
            float2 h0v = *(const float2*)&g_hr0f[parp][gb * H_ + gj];
            float2 gg1 = __ldg((const float2*)&g1f[gj]);
            float2 bb1 = __ldg((const float2*)&be1f[gj]);
            float h0n0 = (h0v.x - m0s[gb]) * rs0s[gb] * sg0[gj]     + sbe0[gj];
            float h0n1 = (h0v.y - m0s[gb]) * rs0s[gb] * sg0[gj + 1] + sbe0[gj + 1];
            float o0 = (h1v.x - m1s[gb]) * rs1s[gb] * gg1.x + bb1.x + h0n0;
            float o1 = (h1v.y - m1s[gb]) * rs1s[gb] * gg1.y + bb1.y + h0n1;
            *(float2*)&out[(size_t)(t - 1) * HB_ + gb * H_ + gj] = make_float2(o0, o1);
        }

        // ---- gemm0: z0rec = h0n(t-1) @ Whh0^T ; K=1024, 16 chunks ----
        {
            const bool live = (t > 0);
            float v[16]; int4 wpf;
            // prefetch chunk 0
            if (live) {
                const float2* s = (const float2*)&g_hr0f[parp][sb * H_ + skq];
                #pragma unroll
                for (int i = 0; i < 8; i++) { float2 f = __ldcg(s + i); v[2*i] = f.x; v[2*i+1] = f.y; }
            }
            wpf = *(const int4*)&g_Whh0l[(size_t)wRglob * 1024 + (wseg << 3)];

            float acc[2][4] = {{0,0,0,0},{0,0,0,0}};
            for (int c = 0; c < 16; c++) {
                __syncthreads();   // prev chunk MMAs done
                // commit staged data
                if (live) {
                    float vn[16];
                    int kbase = (c << 6) + skq;
                    float mm = m0s[sb], rr = rs0s[sb];
                    #pragma unroll
                    for (int i = 0; i < 16; i++)
                        vn[i] = (v[i] - mm) * rr * sg0[kbase + i] + sbe0[kbase + i];
                    stage_store(sAhi, sAlo, sb, skq, vn);
                } else {
                    float vz[16];
                    #pragma unroll
                    for (int i = 0; i < 16; i++) vz[i] = 0.f;
                    stage_store(sAhi, sAlo, sb, skq, vz);
                }
                *(int4*)&sWlo[wr * 72 + (wseg << 3)] = wpf;
                __syncthreads();
                // prefetch next chunk
                if (c + 1 < 16) {
                    if (live) {
                        const float2* s = (const float2*)&g_hr0f[parp][sb * H_ + ((c + 1) << 6) + skq];
                        #pragma unroll
                        for (int i = 0; i < 8; i++) { float2 f = __ldcg(s + i); v[2*i] = f.x; v[2*i+1] = f.y; }
                    }
                    wpf = *(const int4*)&g_Whh0l[(size_t)wRglob * 1024 + ((c + 1) << 6) + (wseg << 3)];
                }
                // MMAs
                const __half* bhR = sw0 + (wn * 8 + fg) * 1032 + (c << 6) + (ft << 1);
                const __half* blR = sWlo + (wn * 8 + fg) * 72 + (ft << 1);
                #pragma unroll
                for (int kk = 0; kk < 4; kk++) {
                    uint32_t bh0 = *(const uint32_t*)(bhR + (kk << 4));
                    uint32_t bh1 = *(const uint32_t*)(bhR + (kk << 4) + 8);
                    uint32_t bl0 = *(const uint32_t*)(blR + (kk << 4));
                    uint32_t bl1 = *(const uint32_t*)(blR + (kk << 4) + 8);
                    #pragma unroll
                    for (int mt = 0; mt < 2; mt++) {
                        int r0 = ((wm << 5) + (mt << 4) + fg) * 66 + (kk << 4) + (ft << 1);
                        int r1 = r0 + 8 * 66;
                        uint32_t ah0 = *(const uint32_t*)(sAhi + r0), ah1 = *(const uint32_t*)(sAhi + r1);
                        uint32_t ah2 = *(const uint32_t*)(sAhi + r0 + 8), ah3 = *(const uint32_t*)(sAhi + r1 + 8);
                        uint32_t al0 = *(const uint32_t*)(sAlo + r0), al1 = *(const uint32_t*)(sAlo + r1);
                        uint32_t al2 = *(const uint32_t*)(sAlo + r0 + 8), al3 = *(const uint32_t*)(sAlo + r1 + 8);
                        mma16816(acc[mt], ah0, ah1, ah2, ah3, bh0, bh1);
                        mma16816(acc[mt], al0, al1, al2, al3, bh0, bh1);
                        mma16816(acc[mt], ah0, ah1, ah2, ah3, bl0, bl1);
                    }
                }
            }
            __syncthreads();
            #pragma unroll
            for (int mt = 0; mt < 2; mt++) {
                int row = (wm << 5) + (mt << 4) + fg;
                int col = (wn << 3) + (ft << 1);
                zbuf[row * 33 + col]           = acc[mt][0];
                zbuf[row * 33 + col + 1]       = acc[mt][1];
                zbuf[(row + 8) * 33 + col]     = acc[mt][2];
                zbuf[(row + 8) * 33 + col + 1] = acc[mt][3];
            }
            __syncthreads();
        }

        // ---- gates0 ----
        {
            size_t pb = (size_t)t * PRE_T + (size_t)gb * G4_ + gj;
            float2 pi = *(const float2*)&g_pre0f[pb];
            float2 pf = *(const float2*)&g_pre0f[pb + 1024];
            float2 pg = *(const float2*)&g_pre0f[pb + 2048];
            float2 po = *(const float2*)&g_pre0f[pb + 3072];
            const float* zr = zbuf + gb * 33;
            float h[2];
            #pragma unroll
            for (int u = 0; u < 2; u++) {
                int jju = gjj + u;
                float zi = zr[jju]      + (u ? pi.y : pi.x) + b0sum[jju];
                float zf = zr[8 + jju]  + (u ? pf.y : pf.x) + b0sum[8 + jju];
                float zg = zr[16 + jju] + (u ? pg.y : pg.x) + b0sum[16 + jju];
                float zo = zr[24 + jju] + (u ? po.y : po.x) + b0sum[24 + jju];
                c0r[u] = sigf_(zf) * c0r[u] + sigf_(zi) * tanhf(zg);
                h[u] = sigf_(zo) * tanhf(c0r[u]);
            }
            *(float2*)&g_hr0f[par][gb * H_ + gj] = make_float2(h[0], h[1]);
            float ps = h[0] + h[1], ss = h[0]*h[0] + h[1]*h[1];
            ps += __shfl_xor_sync(~0u, ps, 1); ss += __shfl_xor_sync(~0u, ss, 1);
            ps += __shfl_xor_sync(~0u, ps, 2); ss += __shfl_xor_sync(~0u, ss, 2);
            if ((lane & 3) == 0) g_p0[par][gb][cta] = make_float2(ps, ss);
        }

        gbar(target);

        // ================= PHASE B =================
        finalize_stats(&g_p0[par][0][0], m0s, rs0s, tid);
        __syncthreads();

        // ---- gemm1: z1rec = [h0n(t) | h1n(t-1)] @ Wcat1^T ; K=2048, 32 chunks ----
        {
            float v[16]; int4 wpf;
            {   // prefetch chunk 0 (h0n part)
                const float2* s = (const float2*)&g_hr0f[par][sb * H_ + skq];
                #pragma unroll
                for (int i = 0; i < 8; i++) { float2 f = __ldcg(s + i); v[2*i] = f.x; v[2*i+1] = f.y; }
            }
            wpf = *(const int4*)&g_Wcat1l[(size_t)wRglob * 2048 + (wseg << 3)];

            float acc[2][4] = {{0,0,0,0},{0,0,0,0}};
            for (int c = 0; c < 32; c++) {
                __syncthreads();
                // commit staged
                if (c < 16) {
                    float vn[16];
                    int kbase = (c << 6) + skq;
                    float mm = m0s[sb], rr = rs0s[sb];
                    #pragma unroll
                    for (int i = 0; i < 16; i++)
                        vn[i] = (v[i] - mm) * rr * sg0[kbase + i] + sbe0[kbase + i];
                    stage_store(sAhi, sAlo, sb, skq, vn);
                } else if (t > 0) {
                    stage_store(sAhi, sAlo, sb, skq, v);   // already h1n(t-1) values
                } else {
                    float vz[16];
                    #pragma unroll
                    for (int i = 0; i < 16; i++) vz[i] = 0.f;
                    stage_store(sAhi, sAlo, sb, skq, vz);
                }
                *(int4*)&sWlo[wr * 72 + (wseg << 3)] = wpf;
                __syncthreads();
                // prefetch next
                if (c + 1 < 32) {
                    int cn = c + 1;
                    if (cn < 16) {
                        const float2* s = (const float2*)&g_hr0f[par][sb * H_ + (cn << 6) + skq];
                        #pragma unroll
                        for (int i = 0; i < 8; i++) { float2 f = __ldcg(s + i); v[2*i] = f.x; v[2*i+1] = f.y; }
                    } else if (t > 0) {
                        const float2* s = (const float2*)&out[(size_t)(t - 1) * HB_ + sb * H_ + ((cn - 16) << 6) + skq];
                        #pragma unroll
                        for (int i = 0; i < 8; i++) { float2 f = __ldcg(s + i); v[2*i] = f.x; v[2*i+1] = f.y; }
                    }
                    wpf = *(const int4*)&g_Wcat1l[(size_t)wRglob * 2048 + (cn << 6) + (wseg << 3)];
                }
                // MMAs
                const __half* bhR = sw1 + (wn * 8 + fg) * 2056 + (c << 6) + (ft << 1);
                const __half* blR = sWlo + (wn * 8 + fg) * 72 + (ft << 1);
                #pragma unroll
                for (int kk = 0; kk < 4; kk++) {
                    uint32_t bh0 = *(const uint32_t*)(bhR + (kk << 4));
                    uint32_t bh1 = *(const uint32_t*)(bhR + (kk << 4) + 8);
                    uint32_t bl0 = *(const uint32_t*)(blR + (kk << 4));
                    uint32_t bl1 = *(const uint32_t*)(blR + (kk << 4) + 8);
                    #pragma unroll
                    for (int mt = 0; mt < 2; mt++) {
                        int r0 = ((wm << 5) + (mt << 4) + fg) * 66 + (kk << 4) + (ft << 1);
                        int r1 = r0 + 8 * 66;
                        uint32_t ah0 = *(const uint32_t*)(sAhi + r0), ah1 = *(const uint32_t*)(sAhi + r1);
                        uint32_t ah2 = *(const uint32_t*)(sAhi + r0 + 8), ah3 = *(const uint32_t*)(sAhi + r1 + 8);
                        uint32_t al0 = *(const uint32_t*)(sAlo + r0), al1 = *(const uint32_t*)(sAlo + r1);
                        uint32_t al2 = *(const uint32_t*)(sAlo + r0 + 8), al3 = *(const uint32_t*)(sAlo + r1 + 8);
                        mma16816(acc[mt], ah0, ah1, ah2, ah3, bh0, bh1);
                        mma16816(acc[mt], al0, al1, al2, al3, bh0, bh1);
                        mma16816(acc[mt], ah0, ah1, ah2, ah3, bl0, bl1);
                    }
                }
            }
            __syncthreads();
            #pragma unroll
            for (int mt = 0; mt < 2; mt++) {
                int row = (wm << 5) + (mt << 4) + fg;
                int col = (wn << 3) + (ft << 1);
                zbuf[row * 33 + col]           = acc[mt][0];
                zbuf[row * 33 + col + 1]       = acc[mt][1];
                zbuf[(row + 8) * 33 + col]     = acc[mt][2];
                zbuf[(row + 8) * 33 + col + 1] = acc[mt][3];
            }
            __syncthreads();
        }

        // ---- gates1 ----
        {
            const float* zr = zbuf + gb * 33;
            float h[2];
            #pragma unroll
            for (int u = 0; u < 2; u++) {
                int jju = gjj + u;
                float zi = zr[jju]      + b1sum[jju];
                float zf = zr[8 + jju]  + b1sum[8 + jju];
                float zg = zr[16 + jju] + b1sum[16 + jju];
                float zo = zr[24 + jju] + b1sum[24 + jju];
                c1r[u] = sigf_(zf) * c1r[u] + sigf_(zi) * tanhf(zg);
                h[u] = sigf_(zo) * tanhf(c1r[u]);
            }
            *(float2*)&g_hr1f[par][gb * H_ + gj] = make_float2(h[0], h[1]);
            float ps = h[0] + h[1], ss = h[0]*h[0] + h[1]*h[1];
            ps += __shfl_xor_sync(~0u, ps, 1); ss += __shfl_xor_sync(~0u, ss, 1);
            ps += __shfl_xor_sync(~0u, ps, 2); ss += __shfl_xor_sync(~0u, ss, 2);
            if ((lane & 3) == 0) g_p1[par][gb][cta] = make_float2(ps, ss);
        }

        gbar(target);
    }

    // ================= EPILOGUE =================
    {
        const int par = (S_ - 1) & 1;   // 1
        finalize_stats(&g_p1[par][0][0], m1s, rs1s, tid);
        __syncthreads();
        float2 h1v = *(const float2*)&g_hr1f[par][gb * H_ + gj];
        float2 h0v = *(const float2*)&g_hr0f[par][gb * H_ + gj];
        float2 gg1 = __ldg((const float2*)&g1f[gj]);
        float2 bb1 = __ldg((const float2*)&be1f[gj]);
        float h0n0 = (h0v.x - m0s[gb]) * rs0s[gb] * sg0[gj]     + sbe0[gj];
        float h0n1 = (h0v.y - m0s[gb]) * rs0s[gb] * sg0[gj + 1] + sbe0[gj + 1];
        float o0 = (h1v.x - m1s[gb]) * rs1s[gb] * gg1.x + bb1.x + h0n0;
        float o1 = (h1v.y - m1s[gb]) * rs1s[gb] * gg1.y + bb1.y + h0n1;
        *(float2*)&out[(size_t)(S_ - 1) * HB_ + gb * H_ + gj] = make_float2(o0, o1);
        if (has_tail) {
            float* tail = out + (size_t)S_ * HB_;
            *(float2*)&tail[gb * H_ + gj]           = make_float2(h0n0, h0n1);
            *(float2*)&tail[HB_ + gb * H_ + gj]     = make_float2(c0r[0], c0r[1]);
            *(float2*)&tail[2 * HB_ + gb * H_ + gj] = make_float2(o0, o1);
            *(float2*)&tail[3 * HB_ + gb * H_ + gj] = make_float2(c1r[0], c1r[1]);
        }
    }
}

extern "C" void kernel_launch(void* const* d_in, const int* in_sizes, int n_in,
                              void* d_out, int out_size) {
    const float* X    = (const float*)d_in[0];
    const float* Wih0 = (const float*)d_in[1];
    const float* Whh0 = (const float*)d_in[2];
    const float* bih0 = (const float*)d_in[3];
    const float* bhh0 = (const float*)d_in[4];
    const float* g0   = (const float*)d_in[5];
    const float* be0  = (const float*)d_in[6];
    const float* Wih1 = (const float*)d_in[7];
    const float* Whh1 = (const float*)d_in[8];
    const float* bih1 = (const float*)d_in[9];
    const float* bhh1 = (const float*)d_in[10];
    const float* g1   = (const float*)d_in[11];
    const float* be1  = (const float*)d_in[12];
    float* out = (float*)d_out;

    static int smem_set = 0;
    if (!smem_set) {
        cudaFuncSetAttribute(lstm_persist, cudaFuncAttributeMaxDynamicSharedMemorySize, SMEM_BYTES);
        smem_set = 1;
    }

    int has_tail = (out_size >= S_ * HB_ + 4 * HB_) ? 1 : 0;

    init_all<<<8192, 1024>>>(Wih0, Whh0, Wih1, Whh1);
    dim3 pg(64, (S_ * B_) / 128);
    pre_gemm<<<pg, 256>>>(X);
    lstm_persist<<<NCTA, TPB, SMEM_BYTES>>>(bih0, bhh0, g0, be0, bih1, bhh1, g1, be1, out, has_tail);
}

// round 10
// speedup vs baseline: 1.0011x; 1.0011x over previous
#include <cuda_runtime.h>
#include <cuda_fp16.h>
#include <cstdint>

#define S_ 512
#define B_ 64
#define D_ 1024
#define H_ 1024
#define G4_ 4096
#define HB_ (B_ * H_)
#define PRE_T (B_ * G4_)
#define NCTA 128
#define TPB 256

// ---------------- persistent device scratch ----------------
__device__ __half g_Wih0h [G4_ * D_];
__device__ __half g_Wih0l [G4_ * D_];
__device__ __half g_Whh0h [G4_ * H_];
__device__ __half g_Whh0l [G4_ * H_];
__device__ __half g_Wcat1h[G4_ * 2 * H_];
__device__ __half g_Wcat1l[G4_ * 2 * H_];
__device__ float  g_pre0f [(size_t)S_ * PRE_T];   // 512 MB fp32
__device__ float  g_hr0f[2][HB_];
__device__ float  g_hr1f[2][HB_];
__device__ float2 g_p0[2][B_][NCTA];
__device__ float2 g_p1[2][B_][NCTA];
__device__ unsigned g_barcnt;

// ---------------- SMEM layout (bytes) ----------------
#define SW1_OFF   0        // 32*2056 half = 131584
#define SW0_OFF   131584   // 32*1032 half = 66048
#define SAHI_OFF  197632   // 64*66 half = 8448 (zbuf aliases here)
#define SALO_OFF  206080   // 8448
#define SWLO_OFF  214528   // 32*72 half = 4608
#define SG0_OFF   219136   // 1024 f = 4096
#define SBE0_OFF  223232   // 4096
#define ST_OFF    227328   // 6*64 f = 1536
#define BS_OFF    228864   // 64 f = 256
#define SMEM_BYTES 229120

__device__ __forceinline__ void mma16816(float* c,
    uint32_t a0, uint32_t a1, uint32_t a2, uint32_t a3, uint32_t b0, uint32_t b1)
{
    asm volatile(
        "mma.sync.aligned.m16n8k16.row.col.f32.f16.f16.f32 "
        "{%0,%1,%2,%3}, {%4,%5,%6,%7}, {%8,%9}, {%0,%1,%2,%3};\n"
        : "+f"(c[0]), "+f"(c[1]), "+f"(c[2]), "+f"(c[3])
        : "r"(a0), "r"(a1), "r"(a2), "r"(a3), "r"(b0), "r"(b1));
}
__device__ __forceinline__ float sigf_(float x) { return 1.0f / (1.0f + __expf(-x)); }

__device__ __forceinline__ void gbar(unsigned& target) {
    __syncthreads();
    if (threadIdx.x == 0) {
        __threadfence();
        atomicAdd(&g_barcnt, 1u);
        target += NCTA;
        volatile unsigned* p = &g_barcnt;
        unsigned spins = 0;
        while (*p < target) {
            __nanosleep(32);
            if (++spins > 100000000u) break;   // convert pathological hang into visible failure
        }
        __threadfence();
    }
    __syncthreads();
}

// deterministic stats: sum 128 CTA partials in fixed order
__device__ __forceinline__ void finalize_stats(const float2* p, float* m, float* rs, int tid) {
    int b = tid >> 2, q = tid & 3;
    const float2* src = p + b * NCTA + q * 32;
    float s = 0.f, ss = 0.f;
    #pragma unroll
    for (int i = 0; i < 32; i++) { float2 v = __ldcg(src + i); s += v.x; ss += v.y; }
    s += __shfl_xor_sync(~0u, s, 1); ss += __shfl_xor_sync(~0u, ss, 1);
    s += __shfl_xor_sync(~0u, s, 2); ss += __shfl_xor_sync(~0u, ss, 2);
    if (q == 0) {
        float mm = s * (1.0f / H_);
        float var = ss * (1.0f / H_) - mm * mm;
        m[b] = mm; rs[b] = rsqrtf(var + 1e-5f);
    }
}

// split 16 fp32 values into hi/lo fp16 and store in staged A buffers
__device__ __forceinline__ void stage_store(__half* sAhi, __half* sAlo, int sb, int skq,
                                            const float* v)
{
    __half2* dh = (__half2*)(sAhi + sb * 66 + skq);
    __half2* dl = (__half2*)(sAlo + sb * 66 + skq);
    #pragma unroll
    for (int i = 0; i < 8; i++) {
        float x = v[2*i], y = v[2*i+1];
        __half hx = __float2half_rn(x), hy = __float2half_rn(y);
        __half lx = __float2half_rn(x - __half2float(hx));
        __half ly = __float2half_rn(y - __half2float(hy));
        dh[i] = __halves2half2(hx, hy);
        dl[i] = __halves2half2(lx, ly);
    }
}

// ---------------- init ----------------
__global__ __launch_bounds__(1024) void init_all(
    const float* __restrict__ Wih0, const float* __restrict__ Whh0,
    const float* __restrict__ Wih1, const float* __restrict__ Whh1)
{
    int i = blockIdx.x * blockDim.x + threadIdx.x;   // covers 8,388,608
    {
        int n = i >> 11, k = i & 2047;
        float w = (k < 1024) ? Wih1[n * 1024 + k] : Whh1[n * 1024 + (k - 1024)];
        __half hi = __float2half_rn(w);
        g_Wcat1h[i] = hi;
        g_Wcat1l[i] = __float2half_rn(w - __half2float(hi));
    }
    if (i < G4_ * D_) {
        float w = Wih0[i];
        __half hi = __float2half_rn(w);
        g_Wih0h[i] = hi;
        g_Wih0l[i] = __float2half_rn(w - __half2float(hi));
        w = Whh0[i];
        hi = __float2half_rn(w);
        g_Whh0h[i] = hi;
        g_Whh0l[i] = __float2half_rn(w - __half2float(hi));
    }
    if (i == 0) g_barcnt = 0u;
}

// ---------------- pre0f = X @ Wih0^T (fp32 out, hi/lo 3-MMA) ----------------
__global__ __launch_bounds__(256) void pre_gemm(const float* __restrict__ X)
{
    int n0 = blockIdx.x << 6;
    size_t m0 = (size_t)blockIdx.y << 7;
    int w = threadIdx.x >> 5, lane = threadIdx.x & 31;
    int g = lane >> 2, t = lane & 3;
    size_t mr = m0 + (w << 4) + g;

    const float* X0 = X + mr * D_ + (t << 1);
    const float* X1 = X0 + 8 * D_;

    float acc[8][4];
    #pragma unroll
    for (int s = 0; s < 8; s++) { acc[s][0]=acc[s][1]=acc[s][2]=acc[s][3]=0.f; }

    for (int k = 0; k < D_; k += 16) {
        uint32_t ah[4], al[4];
        float2 f;
        #pragma unroll
        for (int q = 0; q < 4; q++) {
            const float* src = (q & 1) ? X1 : X0;
            int ko = k + ((q >> 1) << 3);
            f = *(const float2*)(src + ko);
            __half hx = __float2half_rn(f.x), hy = __float2half_rn(f.y);
            __half lx = __float2half_rn(f.x - __half2float(hx));
            __half ly = __float2half_rn(f.y - __half2float(hy));
            __half2 hh = __halves2half2(hx, hy), ll = __halves2half2(lx, ly);
            ah[q] = *(uint32_t*)&hh; al[q] = *(uint32_t*)&ll;
        }
        #pragma unroll
        for (int s = 0; s < 8; s++) {
            size_t roff = (size_t)(n0 + s * 8 + g) * D_ + (t << 1) + k;
            uint32_t bh0 = *(const uint32_t*)(g_Wih0h + roff);
            uint32_t bh1 = *(const uint32_t*)(g_Wih0h + roff + 8);
            uint32_t bl0 = *(const uint32_t*)(g_Wih0l + roff);
            uint32_t bl1 = *(const uint32_t*)(g_Wih0l + roff + 8);
            mma16816(acc[s], ah[0], ah[1], ah[2], ah[3], bh0, bh1);
            mma16816(acc[s], al[0], al[1], al[2], al[3], bh0, bh1);
            mma16816(acc[s], ah[0], ah[1], ah[2], ah[3], bl0, bl1);
        }
    }
    #pragma unroll
    for (int s = 0; s < 8; s++) {
        int col = n0 + s * 8 + (t << 1);
        *(float2*)&g_pre0f[mr * G4_ + col]       = make_float2(acc[s][0], acc[s][1]);
        *(float2*)&g_pre0f[(mr + 8) * G4_ + col] = make_float2(acc[s][2], acc[s][3]);
    }
}

// ---------------- the persistent recurrence kernel ----------------
__global__ __launch_bounds__(TPB, 1) void lstm_persist(
    const float* __restrict__ bih0, const float* __restrict__ bhh0,
    const float* __restrict__ g0f,  const float* __restrict__ be0f,
    const float* __restrict__ bih1, const float* __restrict__ bhh1,
    const float* __restrict__ g1f,  const float* __restrict__ be1f,
    float* __restrict__ out, int has_tail)
{
    extern __shared__ __align__(16) char smem[];
    __half* sw1  = (__half*)(smem + SW1_OFF);
    __half* sw0  = (__half*)(smem + SW0_OFF);
    __half* sAhi = (__half*)(smem + SAHI_OFF);
    __half* sAlo = (__half*)(smem + SALO_OFF);
    __half* sWlo = (__half*)(smem + SWLO_OFF);
    float*  zbuf = (float*)(smem + SAHI_OFF);   // alias (used post-gemm)
    float*  sg0  = (float*)(smem + SG0_OFF);
    float*  sbe0 = (float*)(smem + SBE0_OFF);
    float*  m0s  = (float*)(smem + ST_OFF);
    float*  rs0s = m0s + 64;
    float*  m1s  = m0s + 128;
    float*  rs1s = m0s + 192;
    float*  b0sum = (float*)(smem + BS_OFF);
    float*  b1sum = b0sum + 32;

    const int tid = threadIdx.x;
    const int cta = blockIdx.x;
    const int j0 = cta << 3;
    const int lane = tid & 31, wid = tid >> 5;
    const int fg = lane >> 2, ft = lane & 3;
    const int wn = wid & 3, wm = wid >> 2;       // 4 n-groups x 2 m-groups
    // gates mapping: thread -> (batch gb, column pair gjj)
    const int gb = tid >> 2;
    const int gjj = (tid & 3) << 1;
    const int gj = j0 + gjj;
    // staging mapping
    const int sb = tid >> 2;                     // batch row
    const int skq = (tid & 3) << 4;              // 16 halves per thread
    // Wlo staging mapping
    const int wr = tid >> 3, wseg = tid & 7;
    const int wRglob = ((wr >> 3) << 10) + j0 + (wr & 7);

    // ---- preload SMEM ----
    for (int idx = tid; idx < 32 * 128; idx += TPB) {
        int n = idx >> 7, kc = (idx & 127) << 3;
        int row = ((n >> 3) << 10) + j0 + (n & 7);
        *(int4*)&sw0[n * 1032 + kc] = *(const int4*)&g_Whh0h[(size_t)row * 1024 + kc];
    }
    for (int idx = tid; idx < 32 * 256; idx += TPB) {
        int n = idx >> 8, kc = (idx & 255) << 3;
        int row = ((n >> 3) << 10) + j0 + (n & 7);
        *(int4*)&sw1[n * 2056 + kc] = *(const int4*)&g_Wcat1h[(size_t)row * 2048 + kc];
    }
    for (int idx = tid; idx < 1024; idx += TPB) {
        sg0[idx] = g0f[idx]; sbe0[idx] = be0f[idx];
    }
    if (tid < 32) {
        int col = ((tid >> 3) << 10) + j0 + (tid & 7);
        b0sum[tid] = bih0[col] + bhh0[col];
        b1sum[tid] = bih1[col] + bhh1[col];
    }
    __syncthreads();

    float c0r[2] = {0.f, 0.f}, c1r[2] = {0.f, 0.f};
    unsigned target = 0;

    for (int t = 0; t < S_; t++) {
        const int par = t & 1, parp = par ^ 1;

        // ================= PHASE A =================
        if (t > 0) {
            finalize_stats(&g_p1[parp][0][0], m1s, rs1s, tid);
            __syncthreads();
            float2 h1v = *(const float2*)&g_hr1f[parp][gb * H_ + gj];
            float2 h0v = *(const float2*)&g_hr0f[parp][gb * H_ + gj];
            float2 gg1 = __ldg((const float2*)&g1f[gj]);
            float2 bb1 = __ldg((const float2*)&be1f[gj]);
            float h0n0 = (h0v.x - m0s[gb]) * rs0s[gb] * sg0[gj]     + sbe0[gj];
            float h0n1 = (h0v.y - m0s[gb]) * rs0s[gb] * sg0[gj + 1] + sbe0[gj + 1];
            float o0 = (h1v.x - m1s[gb]) * rs1s[gb] * gg1.x + bb1.x + h0n0;
            float o1 = (h1v.y - m1s[gb]) * rs1s[gb] * gg1.y + bb1.y + h0n1;
            *(float2*)&out[(size_t)(t - 1) * HB_ + gb * H_ + gj] = make_float2(o0, o1);
        }

        // ---- gemm0: z0rec = h0n(t-1) @ Whh0^T ; K=1024, 16 chunks ----
        {
            const bool live = (t > 0);
            float v[16]; int4 wpf;
            // prefetch chunk 0
            if (live) {
                const float2* s = (const float2*)&g_hr0f[parp][sb * H_ + skq];
                #pragma unroll
                for (int i = 0; i < 8; i++) { float2 f = __ldcg(s + i); v[2*i] = f.x; v[2*i+1] = f.y; }
            }
            wpf = *(const int4*)&g_Whh0l[(size_t)wRglob * 1024 + (wseg << 3)];

            float acc[2][4] = {{0,0,0,0},{0,0,0,0}};
            for (int c = 0; c < 16; c++) {
                __syncthreads();   // prev chunk MMAs done
                // commit staged data
                if (live) {
                    float vn[16];
                    int kbase = (c << 6) + skq;
                    float mm = m0s[sb], rr = rs0s[sb];
                    #pragma unroll
                    for (int i = 0; i < 16; i++)
                        vn[i] = (v[i] - mm) * rr * sg0[kbase + i] + sbe0[kbase + i];
                    stage_store(sAhi, sAlo, sb, skq, vn);
                } else {
                    float vz[16];
                    #pragma unroll
                    for (int i = 0; i < 16; i++) vz[i] = 0.f;
                    stage_store(sAhi, sAlo, sb, skq, vz);
                }
                *(int4*)&sWlo[wr * 72 + (wseg << 3)] = wpf;
                __syncthreads();
                // prefetch next chunk
                if (c + 1 < 16) {
                    if (live) {
                        const float2* s = (const float2*)&g_hr0f[parp][sb * H_ + ((c + 1) << 6) + skq];
                        #pragma unroll
                        for (int i = 0; i < 8; i++) { float2 f = __ldcg(s + i); v[2*i] = f.x; v[2*i+1] = f.y; }
                    }
                    wpf = *(const int4*)&g_Whh0l[(size_t)wRglob * 1024 + ((c + 1) << 6) + (wseg << 3)];
                }
                // MMAs
                const __half* bhR = sw0 + (wn * 8 + fg) * 1032 + (c << 6) + (ft << 1);
                const __half* blR = sWlo + (wn * 8 + fg) * 72 + (ft << 1);
                #pragma unroll
                for (int kk = 0; kk < 4; kk++) {
                    uint32_t bh0 = *(const uint32_t*)(bhR + (kk << 4));
                    uint32_t bh1 = *(const uint32_t*)(bhR + (kk << 4) + 8);
                    uint32_t bl0 = *(const uint32_t*)(blR + (kk << 4));
                    uint32_t bl1 = *(const uint32_t*)(blR + (kk << 4) + 8);
                    #pragma unroll
                    for (int mt = 0; mt < 2; mt++) {
                        int r0 = ((wm << 5) + (mt << 4) + fg) * 66 + (kk << 4) + (ft << 1);
                        int r1 = r0 + 8 * 66;
                        uint32_t ah0 = *(const uint32_t*)(sAhi + r0), ah1 = *(const uint32_t*)(sAhi + r1);
                        uint32_t ah2 = *(const uint32_t*)(sAhi + r0 + 8), ah3 = *(const uint32_t*)(sAhi + r1 + 8);
                        uint32_t al0 = *(const uint32_t*)(sAlo + r0), al1 = *(const uint32_t*)(sAlo + r1);
                        uint32_t al2 = *(const uint32_t*)(sAlo + r0 + 8), al3 = *(const uint32_t*)(sAlo + r1 + 8);
                        mma16816(acc[mt], ah0, ah1, ah2, ah3, bh0, bh1);
                        mma16816(acc[mt], al0, al1, al2, al3, bh0, bh1);
                        mma16816(acc[mt], ah0, ah1, ah2, ah3, bl0, bl1);
                    }
                }
            }
            __syncthreads();
            #pragma unroll
            for (int mt = 0; mt < 2; mt++) {
                int row = (wm << 5) + (mt << 4) + fg;
                int col = (wn << 3) + (ft << 1);
                zbuf[row * 33 + col]           = acc[mt][0];
                zbuf[row * 33 + col + 1]       = acc[mt][1];
                zbuf[(row + 8) * 33 + col]     = acc[mt][2];
                zbuf[(row + 8) * 33 + col + 1] = acc[mt][3];
            }
            __syncthreads();
        }

        // ---- gates0 ----
        {
            size_t pb = (size_t)t * PRE_T + (size_t)gb * G4_ + gj;
            float2 pi = *(const float2*)&g_pre0f[pb];
            float2 pf = *(const float2*)&g_pre0f[pb + 1024];
            float2 pg = *(const float2*)&g_pre0f[pb + 2048];
            float2 po = *(const float2*)&g_pre0f[pb + 3072];
            const float* zr = zbuf + gb * 33;
            float h[2];
            #pragma unroll
            for (int u = 0; u < 2; u++) {
                int jju = gjj + u;
                float zi = zr[jju]      + (u ? pi.y : pi.x) + b0sum[jju];
                float zf = zr[8 + jju]  + (u ? pf.y : pf.x) + b0sum[8 + jju];
                float zg = zr[16 + jju] + (u ? pg.y : pg.x) + b0sum[16 + jju];
                float zo = zr[24 + jju] + (u ? po.y : po.x) + b0sum[24 + jju];
                c0r[u] = sigf_(zf) * c0r[u] + sigf_(zi) * tanhf(zg);
                h[u] = sigf_(zo) * tanhf(c0r[u]);
            }
            *(float2*)&g_hr0f[par][gb * H_ + gj] = make_float2(h[0], h[1]);
            float ps = h[0] + h[1], ss = h[0]*h[0] + h[1]*h[1];
            ps += __shfl_xor_sync(~0u, ps, 1); ss += __shfl_xor_sync(~0u, ss, 1);
            ps += __shfl_xor_sync(~0u, ps, 2); ss += __shfl_xor_sync(~0u, ss, 2);
            if ((lane & 3) == 0) g_p0[par][gb][cta] = make_float2(ps, ss);
        }

        gbar(target);

        // ================= PHASE B =================
        finalize_stats(&g_p0[par][0][0], m0s, rs0s, tid);
        __syncthreads();

        // ---- gemm1: z1rec = [h0n(t) | h1n(t-1)] @ Wcat1^T ; K=2048, 32 chunks ----
        {
            float v[16]; int4 wpf;
            {   // prefetch chunk 0 (h0n part)
                const float2* s = (const float2*)&g_hr0f[par][sb * H_ + skq];
                #pragma unroll
                for (int i = 0; i < 8; i++) { float2 f = __ldcg(s + i); v[2*i] = f.x; v[2*i+1] = f.y; }
            }
            wpf = *(const int4*)&g_Wcat1l[(size_t)wRglob * 2048 + (wseg << 3)];

            float acc[2][4] = {{0,0,0,0},{0,0,0,0}};
            for (int c = 0; c < 32; c++) {
                __syncthreads();
                // commit staged
                if (c < 16) {
                    float vn[16];
                    int kbase = (c << 6) + skq;
                    float mm = m0s[sb], rr = rs0s[sb];
                    #pragma unroll
                    for (int i = 0; i < 16; i++)
                        vn[i] = (v[i] - mm) * rr * sg0[kbase + i] + sbe0[kbase + i];
                    stage_store(sAhi, sAlo, sb, skq, vn);
                } else if (t > 0) {
                    stage_store(sAhi, sAlo, sb, skq, v);   // already h1n(t-1) values
                } else {
                    float vz[16];
                    #pragma unroll
                    for (int i = 0; i < 16; i++) vz[i] = 0.f;
                    stage_store(sAhi, sAlo, sb, skq, vz);
                }
                *(int4*)&sWlo[wr * 72 + (wseg << 3)] = wpf;
                __syncthreads();
                // prefetch next
                if (c + 1 < 32) {
                    int cn = c + 1;
                    if (cn < 16) {
                        const float2* s = (const float2*)&g_hr0f[par][sb * H_ + (cn << 6) + skq];
                        #pragma unroll
                        for (int i = 0; i < 8; i++) { float2 f = __ldcg(s + i); v[2*i] = f.x; v[2*i+1] = f.y; }
                    } else if (t > 0) {
                        const float2* s = (const float2*)&out[(size_t)(t - 1) * HB_ + sb * H_ + ((cn - 16) << 6) + skq];
                        #pragma unroll
                        for (int i = 0; i < 8; i++) { float2 f = __ldcg(s + i); v[2*i] = f.x; v[2*i+1] = f.y; }
                    }
                    wpf = *(const int4*)&g_Wcat1l[(size_t)wRglob * 2048 + (cn << 6) + (wseg << 3)];
                }
                // MMAs
                const __half* bhR = sw1 + (wn * 8 + fg) * 2056 + (c << 6) + (ft << 1);
                const __half* blR = sWlo + (wn * 8 + fg) * 72 + (ft << 1);
                #pragma unroll
                for (int kk = 0; kk < 4; kk++) {
                    uint32_t bh0 = *(const uint32_t*)(bhR + (kk << 4));
                    uint32_t bh1 = *(const uint32_t*)(bhR + (kk << 4) + 8);
                    uint32_t bl0 = *(const uint32_t*)(blR + (kk << 4));
                    uint32_t bl1 = *(const uint32_t*)(blR + (kk << 4) + 8);
                    #pragma unroll
                    for (int mt = 0; mt < 2; mt++) {
                        int r0 = ((wm << 5) + (mt << 4) + fg) * 66 + (kk << 4) + (ft << 1);
                        int r1 = r0 + 8 * 66;
                        uint32_t ah0 = *(const uint32_t*)(sAhi + r0), ah1 = *(const uint32_t*)(sAhi + r1);
                        uint32_t ah2 = *(const uint32_t*)(sAhi + r0 + 8), ah3 = *(const uint32_t*)(sAhi + r1 + 8);
                        uint32_t al0 = *(const uint32_t*)(sAlo + r0), al1 = *(const uint32_t*)(sAlo + r1);
                        uint32_t al2 = *(const uint32_t*)(sAlo + r0 + 8), al3 = *(const uint32_t*)(sAlo + r1 + 8);
                        mma16816(acc[mt], ah0, ah1, ah2, ah3, bh0, bh1);
                        mma16816(acc[mt], al0, al1, al2, al3, bh0, bh1);
                        mma16816(acc[mt], ah0, ah1, ah2, ah3, bl0, bl1);
                    }
                }
            }
            __syncthreads();
            #pragma unroll
            for (int mt = 0; mt < 2; mt++) {
                int row = (wm << 5) + (mt << 4) + fg;
                int col = (wn << 3) + (ft << 1);
                zbuf[row * 33 + col]           = acc[mt][0];
                zbuf[row * 33 + col + 1]       = acc[mt][1];
                zbuf[(row + 8) * 33 + col]     = acc[mt][2];
                zbuf[(row + 8) * 33 + col + 1] = acc[mt][3];
            }
            __syncthreads();
        }

        // ---- gates1 ----
        {
            const float* zr = zbuf + gb * 33;
            float h[2];
            #pragma unroll
            for (int u = 0; u < 2; u++) {
                int jju = gjj + u;
                float zi = zr[jju]      + b1sum[jju];
                float zf = zr[8 + jju]  + b1sum[8 + jju];
                float zg = zr[16 + jju] + b1sum[16 + jju];
                float zo = zr[24 + jju] + b1sum[24 + jju];
                c1r[u] = sigf_(zf) * c1r[u] + sigf_(zi) * tanhf(zg);
                h[u] = sigf_(zo) * tanhf(c1r[u]);
            }
            *(float2*)&g_hr1f[par][gb * H_ + gj] = make_float2(h[0], h[1]);
            float ps = h[0] + h[1], ss = h[0]*h[0] + h[1]*h[1];
            ps += __shfl_xor_sync(~0u, ps, 1); ss += __shfl_xor_sync(~0u, ss, 1);
            ps += __shfl_xor_sync(~0u, ps, 2); ss += __shfl_xor_sync(~0u, ss, 2);
            if ((lane & 3) == 0) g_p1[par][gb][cta] = make_float2(ps, ss);
        }

        gbar(target);
    }

    // ================= EPILOGUE =================
    {
        const int par = (S_ - 1) & 1;   // 1
        finalize_stats(&g_p1[par][0][0], m1s, rs1s, tid);
        __syncthreads();
        float2 h1v = *(const float2*)&g_hr1f[par][gb * H_ + gj];
        float2 h0v = *(const float2*)&g_hr0f[par][gb * H_ + gj];
        float2 gg1 = __ldg((const float2*)&g1f[gj]);
        float2 bb1 = __ldg((const float2*)&be1f[gj]);
        float h0n0 = (h0v.x - m0s[gb]) * rs0s[gb] * sg0[gj]     + sbe0[gj];
        float h0n1 = (h0v.y - m0s[gb]) * rs0s[gb] * sg0[gj + 1] + sbe0[gj + 1];
        float o0 = (h1v.x - m1s[gb]) * rs1s[gb] * gg1.x + bb1.x + h0n0;
        float o1 = (h1v.y - m1s[gb]) * rs1s[gb] * gg1.y + bb1.y + h0n1;
        *(float2*)&out[(size_t)(S_ - 1) * HB_ + gb * H_ + gj] = make_float2(o0, o1);
        if (has_tail) {
            float* tail = out + (size_t)S_ * HB_;
            *(float2*)&tail[gb * H_ + gj]           = make_float2(h0n0, h0n1);
            *(float2*)&tail[HB_ + gb * H_ + gj]     = make_float2(c0r[0], c0r[1]);
            *(float2*)&tail[2 * HB_ + gb * H_ + gj] = make_float2(o0, o1);
            *(float2*)&tail[3 * HB_ + gb * H_ + gj] = make_float2(c1r[0], c1r[1]);
        }
    }
}

extern "C" void kernel_launch(void* const* d_in, const int* in_sizes, int n_in,
                              void* d_out, int out_size) {
    const float* X    = (const float*)d_in[0];
    const float* Wih0 = (const float*)d_in[1];
    const float* Whh0 = (const float*)d_in[2];
    const float* bih0 = (const float*)d_in[3];
    const float* bhh0 = (const float*)d_in[4];
    const float* g0   = (const float*)d_in[5];
    const float* be0  = (const float*)d_in[6];
    const float* Wih1 = (const float*)d_in[7];
    const float* Whh1 = (const float*)d_in[8];
    const float* bih1 = (const float*)d_in[9];
    const float* bhh1 = (const float*)d_in[10];
    const float* g1   = (const float*)d_in[11];
    const float* be1  = (const float*)d_in[12];
    float* out = (float*)d_out;

    static int smem_set = 0;
    if (!smem_set) {
        cudaFuncSetAttribute(lstm_persist, cudaFuncAttributeMaxDynamicSharedMemorySize, SMEM_BYTES);
        smem_set = 1;
    }

    int has_tail = (out_size >= S_ * HB_ + 4 * HB_) ? 1 : 0;

    init_all<<<8192, 1024>>>(Wih0, Whh0, Wih1, Whh1);
    dim3 pg(64, (S_ * B_) / 128);
    pre_gemm<<<pg, 256>>>(X);
    lstm_persist<<<NCTA, TPB, SMEM_BYTES>>>(bih0, bhh0, g0, be0, bih1, bhh1, g1, be1, out, has_tail);
}

// round 14
// speedup vs baseline: 1.5364x; 1.5347x over previous
#include <cuda_runtime.h>
#include <cuda_fp16.h>
#include <cstdint>

#define S_ 512
#define B_ 64
#define D_ 1024
#define H_ 1024
#define G4_ 4096
#define HB_ (B_ * H_)
#define PRE_T (B_ * G4_)
#define NCTA 128
#define TPB 512

__device__ __half g_Wih0h [G4_ * D_];
__device__ __half g_Wih0l [G4_ * D_];
__device__ __half g_Whh0h [G4_ * H_];
__device__ __half g_Whh0l [G4_ * H_];
__device__ __half g_Wcat1h[G4_ * 2 * H_];
__device__ __half g_Wcat1l[G4_ * 2 * H_];
__device__ float  g_pre0f [(size_t)S_ * PRE_T];
__device__ float  g_hr0f[2][HB_];
__device__ float  g_hr1f[2][HB_];
__device__ float2 g_p0[2][B_][NCTA];
__device__ float2 g_p1[2][B_][NCTA];
__device__ unsigned g_barcnt;

// SMEM layout (bytes)
#define SW1_OFF   0        // 131584
#define SW0_OFF   131584   // 66048
#define SAHI_OFF  197632   // 64*72 half = 9216 (zbuf 8448 aliases)
#define SALO_OFF  206848   // 9216
#define SWLO_OFF  216064   // 4608
#define SG0_OFF   220672   // 4096
#define SBE0_OFF  224768   // 4096
#define ST_OFF    228864   // 1024
#define BS_OFF    229888   // 256
#define SMEM_BYTES 230144

__device__ __forceinline__ void mma16816(float* c,
    uint32_t a0, uint32_t a1, uint32_t a2, uint32_t a3, uint32_t b0, uint32_t b1)
{
    asm volatile(
        "mma.sync.aligned.m16n8k16.row.col.f32.f16.f16.f32 "
        "{%0,%1,%2,%3}, {%4,%5,%6,%7}, {%8,%9}, {%0,%1,%2,%3};\n"
        : "+f"(c[0]), "+f"(c[1]), "+f"(c[2]), "+f"(c[3])
        : "r"(a0), "r"(a1), "r"(a2), "r"(a3), "r"(b0), "r"(b1));
}
__device__ __forceinline__ float sigf_(float x) { return 1.0f / (1.0f + __expf(-x)); }

__device__ __forceinline__ void gbar(unsigned& target) {
    __syncthreads();
    if (threadIdx.x == 0) {
        __threadfence();
        atomicAdd(&g_barcnt, 1u);
        target += NCTA;
        volatile unsigned* p = &g_barcnt;
        unsigned spins = 0;
        while (*p < target) {
            __nanosleep(32);
            if (++spins > 100000000u) break;
        }
        __threadfence();
    }
    __syncthreads();
}

// deterministic stats over 128 CTA partials (512 threads: 8 per batch row)
__device__ __forceinline__ void finalize_stats(const float2* p, float* m, float* rs, int tid) {
    int b = tid >> 3, q = tid & 7;
    const float2* src = p + b * NCTA + q * 16;
    float s = 0.f, ss = 0.f;
    #pragma unroll
    for (int i = 0; i < 16; i++) { float2 v = __ldcg(src + i); s += v.x; ss += v.y; }
    s += __shfl_xor_sync(~0u, s, 1); ss += __shfl_xor_sync(~0u, ss, 1);
    s += __shfl_xor_sync(~0u, s, 2); ss += __shfl_xor_sync(~0u, ss, 2);
    s += __shfl_xor_sync(~0u, s, 4); ss += __shfl_xor_sync(~0u, ss, 4);
    if (q == 0) {
        float mm = s * (1.0f / H_);
        float var = ss * (1.0f / H_) - mm * mm;
        m[b] = mm; rs[b] = rsqrtf(var + 1e-5f);
    }
}

// split 8 fp32 into hi/lo fp16; A row stride = 72 halves
__device__ __forceinline__ void stage_store(__half* sAhi, __half* sAlo, int sb, int skq,
                                            const float* v)
{
    __half2* dh = (__half2*)(sAhi + sb * 72 + skq);
    __half2* dl = (__half2*)(sAlo + sb * 72 + skq);
    #pragma unroll
    for (int i = 0; i < 4; i++) {
        float x = v[2*i], y = v[2*i+1];
        __half hx = __float2half_rn(x), hy = __float2half_rn(y);
        __half lx = __float2half_rn(x - __half2float(hx));
        __half ly = __float2half_rn(y - __half2float(hy));
        dh[i] = __halves2half2(hx, hy);
        dl[i] = __halves2half2(lx, ly);
    }
}

__global__ __launch_bounds__(1024) void init_all(
    const float* __restrict__ Wih0, const float* __restrict__ Whh0,
    const float* __restrict__ Wih1, const float* __restrict__ Whh1)
{
    int i = blockIdx.x * blockDim.x + threadIdx.x;
    {
        int n = i >> 11, k = i & 2047;
        float w = (k < 1024) ? Wih1[n * 1024 + k] : Whh1[n * 1024 + (k - 1024)];
        __half hi = __float2half_rn(w);
        g_Wcat1h[i] = hi;
        g_Wcat1l[i] = __float2half_rn(w - __half2float(hi));
    }
    if (i < G4_ * D_) {
        float w = Wih0[i];
        __half hi = __float2half_rn(w);
        g_Wih0h[i] = hi;
        g_Wih0l[i] = __float2half_rn(w - __half2float(hi));
        w = Whh0[i];
        hi = __float2half_rn(w);
        g_Whh0h[i] = hi;
        g_Whh0l[i] = __float2half_rn(w - __half2float(hi));
    }
    if (i == 0) g_barcnt = 0u;
}

__global__ __launch_bounds__(256) void pre_gemm(const float* __restrict__ X)
{
    int n0 = blockIdx.x << 6;
    size_t m0 = (size_t)blockIdx.y << 7;
    int w = threadIdx.x >> 5, lane = threadIdx.x & 31;
    int g = lane >> 2, t = lane & 3;
    size_t mr = m0 + (w << 4) + g;

    const float* X0 = X + mr * D_ + (t << 1);
    const float* X1 = X0 + 8 * D_;

    float acc[8][4];
    #pragma unroll
    for (int s = 0; s < 8; s++) { acc[s][0]=acc[s][1]=acc[s][2]=acc[s][3]=0.f; }

    for (int k = 0; k < D_; k += 16) {
        uint32_t ah[4], al[4];
        float2 f;
        #pragma unroll
        for (int q = 0; q < 4; q++) {
            const float* src = (q & 1) ? X1 : X0;
            int ko = k + ((q >> 1) << 3);
            f = *(const float2*)(src + ko);
            __half hx = __float2half_rn(f.x), hy = __float2half_rn(f.y);
            __half lx = __float2half_rn(f.x - __half2float(hx));
            __half ly = __float2half_rn(f.y - __half2float(hy));
            __half2 hh = __halves2half2(hx, hy), ll = __halves2half2(lx, ly);
            ah[q] = *(uint32_t*)&hh; al[q] = *(uint32_t*)&ll;
        }
        #pragma unroll
        for (int s = 0; s < 8; s++) {
            size_t roff = (size_t)(n0 + s * 8 + g) * D_ + (t << 1) + k;
            uint32_t bh0 = *(const uint32_t*)(g_Wih0h + roff);
            uint32_t bh1 = *(const uint32_t*)(g_Wih0h + roff + 8);
            uint32_t bl0 = *(const uint32_t*)(g_Wih0l + roff);
            uint32_t bl1 = *(const uint32_t*)(g_Wih0l + roff + 8);
            mma16816(acc[s], ah[0], ah[1], ah[2], ah[3], bh0, bh1);
            mma16816(acc[s], al[0], al[1], al[2], al[3], bh0, bh1);
            mma16816(acc[s], ah[0], ah[1], ah[2], ah[3], bl0, bl1);
        }
    }
    #pragma unroll
    for (int s = 0; s < 8; s++) {
        int col = n0 + s * 8 + (t << 1);
        *(float2*)&g_pre0f[mr * G4_ + col]       = make_float2(acc[s][0], acc[s][1]);
        *(float2*)&g_pre0f[(mr + 8) * G4_ + col] = make_float2(acc[s][2], acc[s][3]);
    }
}

__global__ __launch_bounds__(TPB, 1) void lstm_persist(
    const float* __restrict__ bih0, const float* __restrict__ bhh0,
    const float* __restrict__ g0f,  const float* __restrict__ be0f,
    const float* __restrict__ bih1, const float* __restrict__ bhh1,
    const float* __restrict__ g1f,  const float* __restrict__ be1f,
    float* __restrict__ out, int has_tail)
{
    extern __shared__ __align__(16) char smem[];
    __half* sw1  = (__half*)(smem + SW1_OFF);
    __half* sw0  = (__half*)(smem + SW0_OFF);
    __half* sAhi = (__half*)(smem + SAHI_OFF);
    __half* sAlo = (__half*)(smem + SALO_OFF);
    __half* sWlo = (__half*)(smem + SWLO_OFF);
    float*  zbuf = (float*)(smem + SAHI_OFF);
    float*  sg0  = (float*)(smem + SG0_OFF);
    float*  sbe0 = (float*)(smem + SBE0_OFF);
    float*  m0s  = (float*)(smem + ST_OFF);
    float*  rs0s = m0s + 64;
    float*  m1s  = m0s + 128;
    float*  rs1s = m0s + 192;
    float*  b0sum = (float*)(smem + BS_OFF);
    float*  b1sum = b0sum + 32;

    const int tid = threadIdx.x;
    const int cta = blockIdx.x;
    const int j0 = cta << 3;
    const int lane = tid & 31, wid = tid >> 5;
    const int fg = lane >> 2, ft = lane & 3;
    const int wn = wid & 3, wm = wid >> 2;     // 4 n-frags x 4 m-tiles
    const int gb = tid >> 3, gjj = tid & 7, gj = j0 + gjj;   // gates: 1 col/thread
    const int sb = tid >> 3, skq = (tid & 7) << 3;            // staging: 8 halves/thread
    const int wr = tid >> 3, wseg = tid & 7;                  // Wlo (tid<256)
    const int wRglob = ((wr >> 3) << 10) + j0 + (wr & 7);

    for (int idx = tid; idx < 32 * 128; idx += TPB) {
        int n = idx >> 7, kc = (idx & 127) << 3;
        int row = ((n >> 3) << 10) + j0 + (n & 7);
        *(int4*)&sw0[n * 1032 + kc] = *(const int4*)&g_Whh0h[(size_t)row * 1024 + kc];
    }
    for (int idx = tid; idx < 32 * 256; idx += TPB) {
        int n = idx >> 8, kc = (idx & 255) << 3;
        int row = ((n >> 3) << 10) + j0 + (n & 7);
        *(int4*)&sw1[n * 2056 + kc] = *(const int4*)&g_Wcat1h[(size_t)row * 2048 + kc];
    }
    for (int idx = tid; idx < 1024; idx += TPB) {
        sg0[idx] = g0f[idx]; sbe0[idx] = be0f[idx];
    }
    if (tid < 32) {
        int col = ((tid >> 3) << 10) + j0 + (tid & 7);
        b0sum[tid] = bih0[col] + bhh0[col];
        b1sum[tid] = bih1[col] + bhh1[col];
    }
    __syncthreads();

    float c0r = 0.f, c1r = 0.f;
    unsigned target = 0;

    for (int t = 0; t < S_; t++) {
        const int par = t & 1, parp = par ^ 1;

        // ---------- PHASE A ----------
        if (t > 0) {
            finalize_stats(&g_p1[parp][0][0], m1s, rs1s, tid);
            __syncthreads();
            float h1v = __ldcg(&g_hr1f[parp][gb * H_ + gj]);
            float h0v = __ldcg(&g_hr0f[parp][gb * H_ + gj]);
            float h0n = (h0v - m0s[gb]) * rs0s[gb] * sg0[gj] + sbe0[gj];
            float o = (h1v - m1s[gb]) * rs1s[gb] * __ldg(&g1f[gj]) + __ldg(&be1f[gj]) + h0n;
            out[(size_t)(t - 1) * HB_ + gb * H_ + gj] = o;
        }

        // ---- gemm0: K=1024, 16 chunks ----
        {
            const bool live = (t > 0);
            float v[8]; int4 wpf = make_int4(0,0,0,0);
            if (live) {
                const float2* s = (const float2*)&g_hr0f[parp][sb * H_ + skq];
                #pragma unroll
                for (int i = 0; i < 4; i++) { float2 f = __ldcg(s + i); v[2*i] = f.x; v[2*i+1] = f.y; }
            }
            if (tid < 256) wpf = *(const int4*)&g_Whh0l[(size_t)wRglob * 1024 + (wseg << 3)];

            float acc[4] = {0,0,0,0};
            for (int c = 0; c < 16; c++) {
                __syncthreads();
                if (live) {
                    float vn[8];
                    int kbase = (c << 6) + skq;
                    float mm = m0s[sb], rr = rs0s[sb];
                    #pragma unroll
                    for (int i = 0; i < 8; i++)
                        vn[i] = (v[i] - mm) * rr * sg0[kbase + i] + sbe0[kbase + i];
                    stage_store(sAhi, sAlo, sb, skq, vn);
                } else {
                    float vz[8] = {0,0,0,0,0,0,0,0};
                    stage_store(sAhi, sAlo, sb, skq, vz);
                }
                if (tid < 256) *(int4*)&sWlo[wr * 72 + (wseg << 3)] = wpf;
                __syncthreads();
                if (c + 1 < 16) {
                    if (live) {
                        const float2* s = (const float2*)&g_hr0f[parp][sb * H_ + ((c + 1) << 6) + skq];
                        #pragma unroll
                        for (int i = 0; i < 4; i++) { float2 f = __ldcg(s + i); v[2*i] = f.x; v[2*i+1] = f.y; }
                    }
                    if (tid < 256) wpf = *(const int4*)&g_Whh0l[(size_t)wRglob * 1024 + ((c + 1) << 6) + (wseg << 3)];
                }
                const __half* bhR = sw0 + (wn * 8 + fg) * 1032 + (c << 6) + (ft << 1);
                const __half* blR = sWlo + (wn * 8 + fg) * 72 + (ft << 1);
                #pragma unroll
                for (int kk = 0; kk < 4; kk++) {
                    uint32_t bh0 = *(const uint32_t*)(bhR + (kk << 4));
                    uint32_t bh1 = *(const uint32_t*)(bhR + (kk << 4) + 8);
                    uint32_t bl0 = *(const uint32_t*)(blR + (kk << 4));
                    uint32_t bl1 = *(const uint32_t*)(blR + (kk << 4) + 8);
                    int r0 = ((wm << 4) + fg) * 72 + (kk << 4) + (ft << 1);
                    int r1 = r0 + 8 * 72;
                    uint32_t ah0 = *(const uint32_t*)(sAhi + r0), ah1 = *(const uint32_t*)(sAhi + r1);
                    uint32_t ah2 = *(const uint32_t*)(sAhi + r0 + 8), ah3 = *(const uint32_t*)(sAhi + r1 + 8);
                    uint32_t al0 = *(const uint32_t*)(sAlo + r0), al1 = *(const uint32_t*)(sAlo + r1);
                    uint32_t al2 = *(const uint32_t*)(sAlo + r0 + 8), al3 = *(const uint32_t*)(sAlo + r1 + 8);
                    mma16816(acc, ah0, ah1, ah2, ah3, bh0, bh1);
                    mma16816(acc, al0, al1, al2, al3, bh0, bh1);
                    mma16816(acc, ah0, ah1, ah2, ah3, bl0, bl1);
                }
            }
            __syncthreads();
            {
                int r = (wm << 4) + (lane >> 2), col = (wn << 3) + (ft << 1);
                zbuf[r * 33 + col]           = acc[0];
                zbuf[r * 33 + col + 1]       = acc[1];
                zbuf[(r + 8) * 33 + col]     = acc[2];
                zbuf[(r + 8) * 33 + col + 1] = acc[3];
            }
            __syncthreads();
        }

        // ---- gates0 ----
        {
            size_t pb = (size_t)t * PRE_T + (size_t)gb * G4_ + gj;
            const float* zr = zbuf + gb * 33;
            float zi = zr[gjj]      + __ldcg(&g_pre0f[pb])        + b0sum[gjj];
            float zf = zr[8 + gjj]  + __ldcg(&g_pre0f[pb + 1024]) + b0sum[8 + gjj];
            float zg = zr[16 + gjj] + __ldcg(&g_pre0f[pb + 2048]) + b0sum[16 + gjj];
            float zo = zr[24 + gjj] + __ldcg(&g_pre0f[pb + 3072]) + b0sum[24 + gjj];
            c0r = sigf_(zf) * c0r + sigf_(zi) * tanhf(zg);
            float h = sigf_(zo) * tanhf(c0r);
            g_hr0f[par][gb * H_ + gj] = h;
            float ps = h, ss = h * h;
            ps += __shfl_xor_sync(~0u, ps, 1); ss += __shfl_xor_sync(~0u, ss, 1);
            ps += __shfl_xor_sync(~0u, ps, 2); ss += __shfl_xor_sync(~0u, ss, 2);
            ps += __shfl_xor_sync(~0u, ps, 4); ss += __shfl_xor_sync(~0u, ss, 4);
            if ((lane & 7) == 0) g_p0[par][gb][cta] = make_float2(ps, ss);
        }

        gbar(target);

        // ---------- PHASE B ----------
        finalize_stats(&g_p0[par][0][0], m0s, rs0s, tid);
        __syncthreads();

        // ---- gemm1: K=2048, 32 chunks ----
        {
            float v[8]; int4 wpf = make_int4(0,0,0,0);
            {
                const float2* s = (const float2*)&g_hr0f[par][sb * H_ + skq];
                #pragma unroll
                for (int i = 0; i < 4; i++) { float2 f = __ldcg(s + i); v[2*i] = f.x; v[2*i+1] = f.y; }
            }
            if (tid < 256) wpf = *(const int4*)&g_Wcat1l[(size_t)wRglob * 2048 + (wseg << 3)];

            float acc[4] = {0,0,0,0};
            for (int c = 0; c < 32; c++) {
                __syncthreads();
                if (c < 16) {
                    float vn[8];
                    int kbase = (c << 6) + skq;
                    float mm = m0s[sb], rr = rs0s[sb];
                    #pragma unroll
                    for (int i = 0; i < 8; i++)
                        vn[i] = (v[i] - mm) * rr * sg0[kbase + i] + sbe0[kbase + i];
                    stage_store(sAhi, sAlo, sb, skq, vn);
                } else if (t > 0) {
                    stage_store(sAhi, sAlo, sb, skq, v);
                } else {
                    float vz[8] = {0,0,0,0,0,0,0,0};
                    stage_store(sAhi, sAlo, sb, skq, vz);
                }
                if (tid < 256) *(int4*)&sWlo[wr * 72 + (wseg << 3)] = wpf;
                __syncthreads();
                if (c + 1 < 32) {
                    int cn = c + 1;
                    if (cn < 16) {
                        const float2* s = (const float2*)&g_hr0f[par][sb * H_ + (cn << 6) + skq];
                        #pragma unroll
                        for (int i = 0; i < 4; i++) { float2 f = __ldcg(s + i); v[2*i] = f.x; v[2*i+1] = f.y; }
                    } else if (t > 0) {
                        const float2* s = (const float2*)&out[(size_t)(t - 1) * HB_ + sb * H_ + ((cn - 16) << 6) + skq];
                        #pragma unroll
                        for (int i = 0; i < 4; i++) { float2 f = __ldcg(s + i); v[2*i] = f.x; v[2*i+1] = f.y; }
                    }
                    if (tid < 256) wpf = *(const int4*)&g_Wcat1l[(size_t)wRglob * 2048 + (cn << 6) + (wseg << 3)];
                }
                const __half* bhR = sw1 + (wn * 8 + fg) * 2056 + (c << 6) + (ft << 1);
                const __half* blR = sWlo + (wn * 8 + fg) * 72 + (ft << 1);
                #pragma unroll
                for (int kk = 0; kk < 4; kk++) {
                    uint32_t bh0 = *(const uint32_t*)(bhR + (kk << 4));
                    uint32_t bh1 = *(const uint32_t*)(bhR + (kk << 4) + 8);
                    uint32_t bl0 = *(const uint32_t*)(blR + (kk << 4));
                    uint32_t bl1 = *(const uint32_t*)(blR + (kk << 4) + 8);
                    int r0 = ((wm << 4) + fg) * 72 + (kk << 4) + (ft << 1);
                    int r1 = r0 + 8 * 72;
                    uint32_t ah0 = *(const uint32_t*)(sAhi + r0), ah1 = *(const uint32_t*)(sAhi + r1);
                    uint32_t ah2 = *(const uint32_t*)(sAhi + r0 + 8), ah3 = *(const uint32_t*)(sAhi + r1 + 8);
                    uint32_t al0 = *(const uint32_t*)(sAlo + r0), al1 = *(const uint32_t*)(sAlo + r1);
                    uint32_t al2 = *(const uint32_t*)(sAlo + r0 + 8), al3 = *(const uint32_t*)(sAlo + r1 + 8);
                    mma16816(acc, ah0, ah1, ah2, ah3, bh0, bh1);
                    mma16816(acc, al0, al1, al2, al3, bh0, bh1);
                    mma16816(acc, ah0, ah1, ah2, ah3, bl0, bl1);
                }
            }
            __syncthreads();
            {
                int r = (wm << 4) + (lane >> 2), col = (wn << 3) + (ft << 1);
                zbuf[r * 33 + col]           = acc[0];
                zbuf[r * 33 + col + 1]       = acc[1];
                zbuf[(r + 8) * 33 + col]     = acc[2];
                zbuf[(r + 8) * 33 + col + 1] = acc[3];
            }
            __syncthreads();
        }

        // ---- gates1 ----
        {
            const float* zr = zbuf + gb * 33;
            float zi = zr[gjj]      + b1sum[gjj];
            float zf = zr[8 + gjj]  + b1sum[8 + gjj];
            float zg = zr[16 + gjj] + b1sum[16 + gjj];
            float zo = zr[24 + gjj] + b1sum[24 + gjj];
            c1r = sigf_(zf) * c1r + sigf_(zi) * tanhf(zg);
            float h = sigf_(zo) * tanhf(c1r);
            g_hr1f[par][gb * H_ + gj] = h;
            float ps = h, ss = h * h;
            ps += __shfl_xor_sync(~0u, ps, 1); ss += __shfl_xor_sync(~0u, ss, 1);
            ps += __shfl_xor_sync(~0u, ps, 2); ss += __shfl_xor_sync(~0u, ss, 2);
            ps += __shfl_xor_sync(~0u, ps, 4); ss += __shfl_xor_sync(~0u, ss, 4);
            if ((lane & 7) == 0) g_p1[par][gb][cta] = make_float2(ps, ss);
        }

        gbar(target);
    }

    // ---------- EPILOGUE ----------
    {
        const int par = (S_ - 1) & 1;
        finalize_stats(&g_p1[par][0][0], m1s, rs1s, tid);
        __syncthreads();
        float h1v = __ldcg(&g_hr1f[par][gb * H_ + gj]);
        float h0v = __ldcg(&g_hr0f[par][gb * H_ + gj]);
        float h0n = (h0v - m0s[gb]) * rs0s[gb] * sg0[gj] + sbe0[gj];
        float o = (h1v - m1s[gb]) * rs1s[gb] * __ldg(&g1f[gj]) + __ldg(&be1f[gj]) + h0n;
        out[(size_t)(S_ - 1) * HB_ + gb * H_ + gj] = o;
        if (has_tail) {
            float* tail = out + (size_t)S_ * HB_;
            tail[gb * H_ + gj]           = h0n;
            tail[HB_ + gb * H_ + gj]     = c0r;
            tail[2 * HB_ + gb * H_ + gj] = o;
            tail[3 * HB_ + gb * H_ + gj] = c1r;
        }
    }
}

extern "C" void kernel_launch(void* const* d_in, const int* in_sizes, int n_in,
                              void* d_out, int out_size) {
    const float* X    = (const float*)d_in[0];
    const float* Wih0 = (const float*)d_in[1];
    const float* Whh0 = (const float*)d_in[2];
    const float* bih0 = (const float*)d_in[3];
    const float* bhh0 = (const float*)d_in[4];
    const float* g0   = (const float*)d_in[5];
    const float* be0  = (const float*)d_in[6];
    const float* Wih1 = (const float*)d_in[7];
    const float* Whh1 = (const float*)d_in[8];
    const float* bih1 = (const float*)d_in[9];
    const float* bhh1 = (const float*)d_in[10];
    const float* g1   = (const float*)d_in[11];
    const float* be1  = (const float*)d_in[12];
    float* out = (float*)d_out;

    static int smem_set = 0;
    if (!smem_set) {
        cudaFuncSetAttribute(lstm_persist, cudaFuncAttributeMaxDynamicSharedMemorySize, SMEM_BYTES);
        smem_set = 1;
    }

    int has_tail = (out_size >= S_ * HB_ + 4 * HB_) ? 1 : 0;

    init_all<<<8192, 1024>>>(Wih0, Whh0, Wih1, Whh1);
    dim3 pg(64, (S_ * B_) / 128);
    pre_gemm<<<pg, 256>>>(X);
    lstm_persist<<<NCTA, TPB, SMEM_BYTES>>>(bih0, bhh0, g0, be0, bih1, bhh1, g1, be1, out, has_tail);
}